// round 1
// baseline (speedup 1.0000x reference)
#include <cuda_runtime.h>
#include <math.h>

#define BB 16
#define SS 2048
#define DD 512
#define NGROUPS 8
#define GC 64          // channels per group
#define KW 5
#define STILE 128

// Scratch (device globals -- no allocation allowed)
__device__ float g_actT[BB * DD * SS];   // activated, transposed [b][c][s]
__device__ float g_noise[BB * SS * DD];  // noise [b][s][d]; later reused pattern below
__device__ float g_inv;                  // 1 / max(||freq_filter||, 1e-12)

// ---------------------------------------------------------------- kernel 0
__global__ void k0_norm(const float* __restrict__ ff) {
    __shared__ float red[256];
    int tid = threadIdx.x;
    float v = 0.f;
    for (int i = tid; i < DD; i += 256) { float f = ff[i]; v += f * f; }
    red[tid] = v;
    __syncthreads();
    for (int s = 128; s > 0; s >>= 1) {
        if (tid < s) red[tid] += red[tid + s];
        __syncthreads();
    }
    if (tid == 0) g_inv = 1.0f / fmaxf(sqrtf(red[0]), 1e-12f);
}

// ---------------------------------------------------------------- kernel 1
// filtered = clip(x * fnorm, +-10); grouped conv over seq (K=5, pad 2);
// activated = tanh(conv + b) + 0.1*filtered; write transposed [b][c][s].
__global__ void __launch_bounds__(256) k1_conv(
    const float* __restrict__ x, const float* __restrict__ ff,
    const float* __restrict__ w, const float* __restrict__ cb)
{
    extern __shared__ float sm[];
    float* ysm = sm;                // [64 ch][136] (132 used, s-halo of 2)
    float* wsm = sm + GC * 136;     // [i][k][o] : 64*5*64

    const int g  = blockIdx.y;
    const int b  = blockIdx.z;
    const int s0 = blockIdx.x * STILE;
    const int tid = threadIdx.x;
    const float inv = g_inv;

    // weights: gmem w[(g*64+o)*64+i)*5+k] -> smem wsm[(i*5+k)*64+o]
    for (int idx = tid; idx < GC * GC * KW; idx += 256) {
        int o = idx / (GC * KW);
        int r = idx - o * (GC * KW);
        int i = r / KW;
        int k = r - i * KW;
        wsm[(i * KW + k) * GC + o] = w[((g * GC + o) * GC + i) * KW + k];
    }
    // input tile: filtered, clipped, zero padded
    for (int idx = tid; idx < 132 * GC; idx += 256) {
        int i  = idx & 63;
        int j  = idx >> 6;
        int sg = s0 + j - 2;
        float v = 0.f;
        if (sg >= 0 && sg < SS) {
            int c = g * GC + i;
            v = x[(b * SS + sg) * DD + c] * (ff[c] * inv);
            v = fminf(fmaxf(v, -10.f), 10.f);
        }
        ysm[i * 136 + j] = v;
    }
    __syncthreads();

    const int so = tid & 31;   // 4-s slab
    const int oo = tid >> 5;   // 8-o slab

    float acc[4][8];
#pragma unroll
    for (int a = 0; a < 4; ++a)
#pragma unroll
        for (int c = 0; c < 8; ++c) acc[a][c] = 0.f;

    const float4* wsm4 = (const float4*)wsm;

    for (int i = 0; i < GC; ++i) {
        const float* yr = &ysm[i * 136 + so * 4];
        float4 y0 = *(const float4*)(yr);
        float4 y1 = *(const float4*)(yr + 4);
        float ya[8] = {y0.x, y0.y, y0.z, y0.w, y1.x, y1.y, y1.z, y1.w};
#pragma unroll
        for (int k = 0; k < KW; ++k) {
            float4 w0 = wsm4[(i * KW + k) * 16 + oo * 2];
            float4 w1 = wsm4[(i * KW + k) * 16 + oo * 2 + 1];
            float wv[8] = {w0.x, w0.y, w0.z, w0.w, w1.x, w1.y, w1.z, w1.w};
#pragma unroll
            for (int ts = 0; ts < 4; ++ts)
#pragma unroll
                for (int oc = 0; oc < 8; ++oc)
                    acc[ts][oc] = fmaf(ya[ts + k], wv[oc], acc[ts][oc]);
        }
    }

#pragma unroll
    for (int oc = 0; oc < 8; ++oc) {
        int ol = oo * 8 + oc;
        float bias = cb[g * GC + ol];
        float4 o4;
        float* po = (float*)&o4;
#pragma unroll
        for (int ts = 0; ts < 4; ++ts) {
            float filt = ysm[ol * 136 + so * 4 + ts + 2];
            po[ts] = tanhf(acc[ts][oc] + bias) + 0.1f * filt;
        }
        *(float4*)&g_actT[((b * DD) + g * GC + ol) * SS + s0 + so * 4] = o4;
    }
}

// ---------------------------------------------------------------- kernel 2
// Per block: 8 channels = 4 complex seqs of length 2048.
// z = colA + i*colB ; z' = ifft(fft(z) .* s_sym) ; re/im are the two
// filtered columns (valid because s_sym is real & conjugate-symmetric).
// DIF (natural->bitrev) forward, DIT (bitrev->natural) inverse; scaling
// applied at bit-reversed indices. 1/N folded into the scaling.
__global__ void __launch_bounds__(256) k2_fft()
{
    extern __shared__ float2 Zs[];          // 4*2048 data + 1024 twiddles
    float2* tws = Zs + 4 * 2048;
    const int tid = threadIdx.x;
    const int b  = blockIdx.y;
    const int d0 = blockIdx.x * 8;

    for (int j = tid; j < 1024; j += 256) {
        float sv, cv;
        sincosf(-3.14159265358979323846f * (float)j * (1.0f / 1024.0f), &sv, &cv);
        tws[j] = make_float2(cv, sv);
    }
    for (int idx = tid; idx < 4 * 512; idx += 256) {
        int q = idx >> 9, n4 = idx & 511;
        const float4 ra = *(const float4*)&g_actT[((b * DD) + d0 + 2 * q) * SS + n4 * 4];
        const float4 rb = *(const float4*)&g_actT[((b * DD) + d0 + 2 * q + 1) * SS + n4 * 4];
        float2* zp = Zs + q * 2048 + n4 * 4;
        zp[0] = make_float2(ra.x, rb.x);
        zp[1] = make_float2(ra.y, rb.y);
        zp[2] = make_float2(ra.z, rb.z);
        zp[3] = make_float2(ra.w, rb.w);
    }
    __syncthreads();

    // forward DIF
    int step = 1;
#pragma unroll 1
    for (int span = 1024; span >= 1; span >>= 1, step <<= 1) {
#pragma unroll 1
        for (int it = 0; it < 16; ++it) {
            int bt = tid + it * 256;
            int q = bt >> 10, t = bt & 1023;
            int j = t & (span - 1);
            int a = ((t - j) << 1) + j;
            float2* Zq = Zs + q * 2048;
            float2 u = Zq[a], v = Zq[a + span];
            Zq[a] = make_float2(u.x + v.x, u.y + v.y);
            float2 dd = make_float2(u.x - v.x, u.y - v.y);
            float2 tw = tws[j * step];
            Zq[a + span] = make_float2(dd.x * tw.x - dd.y * tw.y,
                                       dd.x * tw.y + dd.y * tw.x);
        }
        __syncthreads();
    }

    // spectral scaling in bit-reversed domain (+ 1/N)
    for (int idx = tid; idx < 4 * 2048; idx += 256) {
        int p = idx & 2047;
        int k = __brev((unsigned)p) >> 21;     // 11-bit reverse
        int kk = min(k, 2048 - k);
        float base = sqrtf((float)kk * (1.0f / 2048.0f) + 1e-8f);
        base = fminf(fmaxf(base, 1e-8f), 1e6f);
        float sc = (1.0f / base) * (1.0f / 2048.0f);
        Zs[idx].x *= sc;
        Zs[idx].y *= sc;
    }
    __syncthreads();

    // inverse DIT (conjugated twiddles)
    step = 1024;
#pragma unroll 1
    for (int span = 1; span <= 1024; span <<= 1, step >>= 1) {
#pragma unroll 1
        for (int it = 0; it < 16; ++it) {
            int bt = tid + it * 256;
            int q = bt >> 10, t = bt & 1023;
            int j = t & (span - 1);
            int a = ((t - j) << 1) + j;
            float2* Zq = Zs + q * 2048;
            float2 u = Zq[a], v = Zq[a + span];
            float2 tw = tws[j * step];
            float2 vw = make_float2(v.x * tw.x + v.y * tw.y,
                                    v.y * tw.x - v.x * tw.y);
            Zq[a] = make_float2(u.x + vw.x, u.y + vw.y);
            Zq[a + span] = make_float2(u.x - vw.x, u.y - vw.y);
        }
        __syncthreads();
    }

    // clip and store to [b][s][d]
    for (int n = tid; n < 2048; n += 256) {
        float2 z0 = Zs[0 * 2048 + n], z1 = Zs[1 * 2048 + n];
        float2 z2 = Zs[2 * 2048 + n], z3 = Zs[3 * 2048 + n];
        float4 o0 = make_float4(fminf(fmaxf(z0.x, -10.f), 10.f),
                                fminf(fmaxf(z0.y, -10.f), 10.f),
                                fminf(fmaxf(z1.x, -10.f), 10.f),
                                fminf(fmaxf(z1.y, -10.f), 10.f));
        float4 o1 = make_float4(fminf(fmaxf(z2.x, -10.f), 10.f),
                                fminf(fmaxf(z2.y, -10.f), 10.f),
                                fminf(fmaxf(z3.x, -10.f), 10.f),
                                fminf(fmaxf(z3.y, -10.f), 10.f));
        float* dst = &g_noise[(b * SS + n) * DD + d0];
        *(float4*)dst = o0;
        *(float4*)(dst + 4) = o1;
    }
}

// ---------------------------------------------------------------- kernel 3
// LayerNorm over last dim; warp per (b,s) row; result into g_actT (reuse).
__global__ void __launch_bounds__(512) k3_ln(const float* __restrict__ gamma,
                                             const float* __restrict__ beta)
{
    int warp = threadIdx.x >> 5, lane = threadIdx.x & 31;
    int row = blockIdx.x * 16 + warp;              // [0, B*S)
    const float* src = g_noise + row * DD;
    float vals[16];
    float sum = 0.f;
#pragma unroll
    for (int j = 0; j < 16; ++j) {
        float v = src[lane + j * 32];
        vals[j] = v;
        sum += v;
    }
#pragma unroll
    for (int o = 16; o; o >>= 1) sum += __shfl_xor_sync(0xffffffffu, sum, o);
    float mu = sum * (1.0f / 512.0f);
    float sq = 0.f;
#pragma unroll
    for (int j = 0; j < 16; ++j) { float dv = vals[j] - mu; sq += dv * dv; }
#pragma unroll
    for (int o = 16; o; o >>= 1) sq += __shfl_xor_sync(0xffffffffu, sq, o);
    float rstd = rsqrtf(sq * (1.0f / 512.0f) + 1e-5f);
    float* dst = g_actT + row * DD;                // reuse buffer
#pragma unroll
    for (int j = 0; j < 16; ++j) {
        int d = lane + j * 32;
        dst[d] = (vals[j] - mu) * rstd * gamma[d] + beta[d];
    }
}

// ---------------------------------------------------------------- kernel 4
// EMA: m[0]=ln[0]; m[t]=a*ln[t]+(1-a)*m[t-1]. (15/16)^256 ~ 7e-8, so
// chunks of 256 outputs with a 256-step lookback are independent.
__global__ void __launch_bounds__(512) k4_ema(float* __restrict__ out)
{
    const int d  = threadIdx.x;
    const int b  = blockIdx.y;
    const int t0 = blockIdx.x * 256;
    const float* src = g_actT + (b * SS) * DD + d;
    float* dst = out + (b * SS) * DD + d;
    const float a = 0.0625f, na = 0.9375f;
    float m;
    int t;
    if (t0 == 0) {
        m = src[0];
        dst[0] = m;
        t = 1;
    } else {
        m = 0.f;
        t = t0 - 256;
    }
    const int tend = t0 + 256;
    for (; t < t0; ++t) m = a * src[t * DD] + na * m;          // lookback
    for (; t < tend; ++t) {
        m = a * src[t * DD] + na * m;
        dst[t * DD] = m;
    }
}

// ---------------------------------------------------------------- launch
extern "C" void kernel_launch(void* const* d_in, const int* in_sizes, int n_in,
                              void* d_out, int out_size)
{
    const float* x     = (const float*)d_in[0];
    const float* ff    = (const float*)d_in[1];
    const float* cw    = (const float*)d_in[2];
    const float* cb    = (const float*)d_in[3];
    const float* gamma = (const float*)d_in[4];
    const float* beta  = (const float*)d_in[5];
    float* out = (float*)d_out;

    const int k1_smem = (GC * 136 + GC * KW * GC) * (int)sizeof(float);
    const int k2_smem = (4 * 2048 + 1024) * (int)sizeof(float2);
    cudaFuncSetAttribute(k1_conv, cudaFuncAttributeMaxDynamicSharedMemorySize, k1_smem);
    cudaFuncSetAttribute(k2_fft,  cudaFuncAttributeMaxDynamicSharedMemorySize, k2_smem);

    k0_norm<<<1, 256>>>(ff);
    k1_conv<<<dim3(SS / STILE, NGROUPS, BB), 256, k1_smem>>>(x, ff, cw, cb);
    k2_fft<<<dim3(DD / 8, BB), 256, k2_smem>>>();
    k3_ln<<<(BB * SS) / 16, 512>>>(gamma, beta);
    k4_ema<<<dim3(SS / 256, BB), 512>>>(out);
}

// round 2
// speedup vs baseline: 1.4485x; 1.4485x over previous
#include <cuda_runtime.h>
#include <math.h>

#define BB 16
#define SS 2048
#define DD 512
#define NGROUPS 8
#define GC 64          // channels per group
#define KW 5
#define STILE 256      // seq positions per conv block

// Scratch (device globals -- no allocation allowed)
__device__ float g_actT[BB * DD * SS];   // activated, transposed [b][c][s]; later reused for ln out
__device__ float g_noise[BB * SS * DD];  // noise [b][s][d]
__device__ float g_inv;                  // 1 / max(||freq_filter||, 1e-12)

// packed fp32x2 helpers
#define FMA_F32X2(d, a, b, c) \
    asm("fma.rn.f32x2 %0, %1, %2, %3;" : "=l"(d) : "l"(a), "l"(b), "l"(c))
#define PACK2(d, lo, hi) \
    asm("mov.b64 %0, {%1, %2};" : "=l"(d) : "r"(lo), "r"(hi))
#define UNPACK2(lo, hi, s) \
    asm("mov.b64 {%0, %1}, %2;" : "=r"(lo), "=r"(hi) : "l"(s))

__device__ __forceinline__ float2 cmulf(float2 a, float2 b) {
    return make_float2(fmaf(a.x, b.x, -a.y * b.y), fmaf(a.x, b.y, a.y * b.x));
}
__device__ __forceinline__ float2 caddf(float2 a, float2 b) {
    return make_float2(a.x + b.x, a.y + b.y);
}
__device__ __forceinline__ float2 csubf(float2 a, float2 b) {
    return make_float2(a.x - b.x, a.y - b.y);
}

// ---------------------------------------------------------------- kernel 0
__global__ void k0_norm(const float* __restrict__ ff) {
    __shared__ float red[256];
    int tid = threadIdx.x;
    float v = 0.f;
    for (int i = tid; i < DD; i += 256) { float f = ff[i]; v += f * f; }
    red[tid] = v;
    __syncthreads();
    for (int s = 128; s > 0; s >>= 1) {
        if (tid < s) red[tid] += red[tid + s];
        __syncthreads();
    }
    if (tid == 0) g_inv = 1.0f / fmaxf(sqrtf(red[0]), 1e-12f);
}

// ---------------------------------------------------------------- kernel 1
// filtered = clip(x * fnorm, +-10); grouped conv over seq (K=5, pad 2);
// activated = tanh(conv + b) + 0.1*filtered; write transposed [b][c][s].
// 512 threads, 256-seq tile, fp32x2 packed FMAs over output-channel pairs.
__global__ void __launch_bounds__(512) k1_conv(
    const float* __restrict__ x, const float* __restrict__ ff,
    const float* __restrict__ w, const float* __restrict__ cb)
{
    extern __shared__ float sm[];
    float* ysm = sm;                   // [64 ch][264] (260 used: 256 + halo 2+2)
    float* wsm = sm + GC * 264;        // [i][k][o] : 64*5*64

    const int g  = blockIdx.y;
    const int b  = blockIdx.z;
    const int s0 = blockIdx.x * STILE;
    const int tid = threadIdx.x;
    const float inv = g_inv;

    // weights: gmem w[((g*64+o)*64+i)*5+k] -> smem wsm[(i*5+k)*64+o]
    for (int idx = tid; idx < GC * GC * KW; idx += 512) {
        int o = idx / (GC * KW);
        int r = idx - o * (GC * KW);
        int i = r / KW;
        int k = r - i * KW;
        wsm[(i * KW + k) * GC + o] = w[((g * GC + o) * GC + i) * KW + k];
    }
    // input tile: filtered, clipped, zero padded (260 cols)
    for (int idx = tid; idx < 260 * GC; idx += 512) {
        int i  = idx & 63;
        int j  = idx >> 6;
        int sg = s0 + j - 2;
        float v = 0.f;
        if (sg >= 0 && sg < SS) {
            int c = g * GC + i;
            v = x[(b * SS + sg) * DD + c] * (ff[c] * inv);
            v = fminf(fmaxf(v, -10.f), 10.f);
        }
        ysm[i * 264 + j] = v;
    }
    __syncthreads();

    const int so = tid & 63;   // 4-s slab -> covers 256 s
    const int oo = tid >> 6;   // 8-o slab (0..7)

    unsigned long long acc2[4][4];
#pragma unroll
    for (int a = 0; a < 4; ++a)
#pragma unroll
        for (int c = 0; c < 4; ++c) acc2[a][c] = 0ull;

#pragma unroll 2
    for (int i = 0; i < GC; ++i) {
        const float* yr = &ysm[i * 264 + so * 4];
        float4 y0 = *(const float4*)(yr);
        float4 y1 = *(const float4*)(yr + 4);
        float ya[8] = {y0.x, y0.y, y0.z, y0.w, y1.x, y1.y, y1.z, y1.w};
        unsigned long long y2[8];
#pragma unroll
        for (int j = 0; j < 8; ++j) {
            unsigned int u = __float_as_uint(ya[j]);
            PACK2(y2[j], u, u);
        }
#pragma unroll
        for (int k = 0; k < KW; ++k) {
            const float* wr = &wsm[(i * KW + k) * GC + oo * 8];
            ulonglong2 wa = *(const ulonglong2*)(wr);
            ulonglong2 wb = *(const ulonglong2*)(wr + 4);
            unsigned long long w2[4] = {wa.x, wa.y, wb.x, wb.y};
#pragma unroll
            for (int ts = 0; ts < 4; ++ts)
#pragma unroll
                for (int op = 0; op < 4; ++op)
                    FMA_F32X2(acc2[ts][op], y2[ts + k], w2[op], acc2[ts][op]);
        }
    }

#pragma unroll
    for (int op = 0; op < 4; ++op) {
#pragma unroll
        for (int h = 0; h < 2; ++h) {
            int ol = oo * 8 + op * 2 + h;
            float bias = cb[g * GC + ol];
            float4 o4;
            float* po = (float*)&o4;
#pragma unroll
            for (int ts = 0; ts < 4; ++ts) {
                unsigned int lo, hi;
                UNPACK2(lo, hi, acc2[ts][op]);
                float av = __uint_as_float(h ? hi : lo);
                float filt = ysm[ol * 264 + so * 4 + ts + 2];
                po[ts] = tanhf(av + bias) + 0.1f * filt;
            }
            *(float4*)&g_actT[((b * DD) + g * GC + ol) * SS + s0 + so * 4] = o4;
        }
    }
}

// ---------------------------------------------------------------- kernel 2
// Per block: 8 channels = 4 complex seqs of length 2048.
// z = colA + i*colB ; z' = ifft(fft(z) .* s_sym) ; re/im are the two
// filtered columns (s_sym real & conjugate-symmetric).
// Radix-2 DIF forward / DIT inverse, with pairs of stages fused into
// radix-4 passes (same permutation => scaling stays in bit-reversed domain).
__global__ void __launch_bounds__(512) k2_fft()
{
    extern __shared__ float2 Zs[];          // 4*2048 data + 1024 twiddles
    float2* tws = Zs + 4 * 2048;
    const int tid = threadIdx.x;
    const int b  = blockIdx.y;
    const int d0 = blockIdx.x * 8;

    for (int j = tid; j < 1024; j += 512) {
        float sv, cv;
        sincosf(-3.14159265358979323846f * (float)j * (1.0f / 1024.0f), &sv, &cv);
        tws[j] = make_float2(cv, sv);
    }
    for (int idx = tid; idx < 4 * 512; idx += 512) {
        int q = idx >> 9, n4 = idx & 511;
        const float4 ra = *(const float4*)&g_actT[((b * DD) + d0 + 2 * q) * SS + n4 * 4];
        const float4 rb = *(const float4*)&g_actT[((b * DD) + d0 + 2 * q + 1) * SS + n4 * 4];
        float2* zp = Zs + q * 2048 + n4 * 4;
        zp[0] = make_float2(ra.x, rb.x);
        zp[1] = make_float2(ra.y, rb.y);
        zp[2] = make_float2(ra.z, rb.z);
        zp[3] = make_float2(ra.w, rb.w);
    }
    __syncthreads();

    // ---- forward: 5 radix-4 (paired radix-2 DIF) passes, spans (1024,512)...(4,2)
    {
        const int ls_arr[5] = {9, 7, 5, 3, 1};   // log2(s), s = 512,128,32,8,2
#pragma unroll 1
        for (int p = 0; p < 5; ++p) {
            const int ls = ls_arr[p];
            const int s = 1 << ls;
            const int stepA = 512 >> ls;         // stage A: span 2s
#pragma unroll 1
            for (int it = 0; it < 4; ++it) {
                int bt = tid + it * 512;
                int q = bt >> 9, t = bt & 511;
                int j = t & (s - 1);
                int m = t >> ls;
                int a = (m << (ls + 2)) + j;
                float2* Zq = Zs + q * 2048;
                float2 t0 = Zq[a], t1 = Zq[a + s], t2 = Zq[a + 2 * s], t3 = Zq[a + 3 * s];
                float2 w1 = tws[j * stepA];
                float2 w2 = tws[2 * j * stepA];
                float2 A0 = caddf(t0, t2);
                float2 A2 = cmulf(csubf(t0, t2), w1);
                float2 A1 = caddf(t1, t3);
                float2 tmp = cmulf(csubf(t1, t3), w1);
                float2 A3 = make_float2(tmp.y, -tmp.x);       // * (-i)
                Zq[a]         = caddf(A0, A1);
                Zq[a + s]     = cmulf(csubf(A0, A1), w2);
                Zq[a + 2 * s] = caddf(A2, A3);
                Zq[a + 3 * s] = cmulf(csubf(A2, A3), w2);
            }
            __syncthreads();
        }
    }

    // ---- fused: final forward stage (span=1, tw=1) + spectral scaling (bit-rev domain, +1/N)
#pragma unroll 1
    for (int it = 0; it < 8; ++it) {
        int bt = tid + it * 512;
        int q = bt >> 10, p = bt & 1023;
        float2* Zq = Zs + q * 2048;
        float4 zz = *(float4*)&Zq[2 * p];
        float2 u = make_float2(zz.x, zz.y), v = make_float2(zz.z, zz.w);
        float2 r0 = caddf(u, v), r1 = csubf(u, v);
        int k0 = __brev((unsigned)(2 * p)) >> 21;
        int k1 = k0 | 1024;
        int kk0 = min(k0, 2048 - k0);
        int kk1 = 2048 - k1;
        float b0 = fminf(fmaxf(sqrtf((float)kk0 * (1.0f / 2048.0f) + 1e-8f), 1e-8f), 1e6f);
        float b1 = fminf(fmaxf(sqrtf((float)kk1 * (1.0f / 2048.0f) + 1e-8f), 1e-8f), 1e6f);
        float sc0 = (1.0f / b0) * (1.0f / 2048.0f);
        float sc1 = (1.0f / b1) * (1.0f / 2048.0f);
        float4 oz = make_float4(r0.x * sc0, r0.y * sc0, r1.x * sc1, r1.y * sc1);
        *(float4*)&Zq[2 * p] = oz;
    }
    __syncthreads();

    // ---- inverse: 5 radix-4 (paired radix-2 DIT) passes, spans (1,2)...(256,512)
    {
        const int ls_arr[5] = {0, 2, 4, 6, 8};   // s = 1,4,16,64,256
#pragma unroll 1
        for (int p = 0; p < 5; ++p) {
            const int ls = ls_arr[p];
            const int s = 1 << ls;
            const int stepA = 512 >> ls;         // stage A': span 2s
            const int stepB = 1024 >> ls;        // stage B': span s
#pragma unroll 1
            for (int it = 0; it < 4; ++it) {
                int bt = tid + it * 512;
                int q = bt >> 9, t = bt & 511;
                int j = t & (s - 1);
                int m = t >> ls;
                int a = (m << (ls + 2)) + j;
                float2* Zq = Zs + q * 2048;
                float2 t0 = Zq[a], t1 = Zq[a + s], t2 = Zq[a + 2 * s], t3 = Zq[a + 3 * s];
                float2 tw2 = tws[j * stepB];
                float2 cw2 = make_float2(tw2.x, -tw2.y);
                float2 tw1 = tws[j * stepA];
                float2 cw1 = make_float2(tw1.x, -tw1.y);
                float2 v1 = cmulf(t1, cw2), v3 = cmulf(t3, cw2);
                float2 B0 = caddf(t0, v1), B1 = csubf(t0, v1);
                float2 B2 = caddf(t2, v3), B3 = csubf(t2, v3);
                float2 C  = cmulf(B2, cw1);
                float2 E  = cmulf(B3, cw1);
                float2 Ei = make_float2(-E.y, E.x);           // * (+i)
                Zq[a]         = caddf(B0, C);
                Zq[a + 2 * s] = csubf(B0, C);
                Zq[a + s]     = caddf(B1, Ei);
                Zq[a + 3 * s] = csubf(B1, Ei);
            }
            __syncthreads();
        }
    }

    // ---- fused: final inverse stage (span=1024) + clip + store to [b][s][d]
#pragma unroll 1
    for (int it = 0; it < 2; ++it) {
        int n = tid + it * 512;                  // n in [0,1024)
        float2 tw = tws[n];
        float2 cw = make_float2(tw.x, -tw.y);
        float lo[8], hi[8];
#pragma unroll
        for (int q = 0; q < 4; ++q) {
            float2 u = Zs[q * 2048 + n];
            float2 v = Zs[q * 2048 + n + 1024];
            float2 vw = cmulf(v, cw);
            float2 e0 = caddf(u, vw), e1 = csubf(u, vw);
            lo[2 * q]     = fminf(fmaxf(e0.x, -10.f), 10.f);
            lo[2 * q + 1] = fminf(fmaxf(e0.y, -10.f), 10.f);
            hi[2 * q]     = fminf(fmaxf(e1.x, -10.f), 10.f);
            hi[2 * q + 1] = fminf(fmaxf(e1.y, -10.f), 10.f);
        }
        float* dA = &g_noise[(b * SS + n) * DD + d0];
        float* dB = &g_noise[(b * SS + n + 1024) * DD + d0];
        *(float4*)dA       = make_float4(lo[0], lo[1], lo[2], lo[3]);
        *(float4*)(dA + 4) = make_float4(lo[4], lo[5], lo[6], lo[7]);
        *(float4*)dB       = make_float4(hi[0], hi[1], hi[2], hi[3]);
        *(float4*)(dB + 4) = make_float4(hi[4], hi[5], hi[6], hi[7]);
    }
}

// ---------------------------------------------------------------- kernel 3
// LayerNorm over last dim; warp per (b,s) row; float4 IO; result into g_actT.
__global__ void __launch_bounds__(512) k3_ln(const float* __restrict__ gamma,
                                             const float* __restrict__ beta)
{
    int warp = threadIdx.x >> 5, lane = threadIdx.x & 31;
    int row = blockIdx.x * 16 + warp;              // [0, B*S)
    const float* src = g_noise + row * DD;
    float4 v4[4];
    float sum = 0.f;
#pragma unroll
    for (int j = 0; j < 4; ++j) {
        v4[j] = *(const float4*)&src[(lane + j * 32) * 4];
        sum += v4[j].x + v4[j].y + v4[j].z + v4[j].w;
    }
#pragma unroll
    for (int o = 16; o; o >>= 1) sum += __shfl_xor_sync(0xffffffffu, sum, o);
    float mu = sum * (1.0f / 512.0f);
    float sq = 0.f;
#pragma unroll
    for (int j = 0; j < 4; ++j) {
        float a0 = v4[j].x - mu, a1 = v4[j].y - mu, a2 = v4[j].z - mu, a3 = v4[j].w - mu;
        sq += a0 * a0 + a1 * a1 + a2 * a2 + a3 * a3;
    }
#pragma unroll
    for (int o = 16; o; o >>= 1) sq += __shfl_xor_sync(0xffffffffu, sq, o);
    float rstd = rsqrtf(sq * (1.0f / 512.0f) + 1e-5f);
    float* dst = g_actT + row * DD;                // reuse buffer
#pragma unroll
    for (int j = 0; j < 4; ++j) {
        int d = (lane + j * 32) * 4;
        float4 gm = *(const float4*)&gamma[d];
        float4 bt = *(const float4*)&beta[d];
        float4 o4;
        o4.x = (v4[j].x - mu) * rstd * gm.x + bt.x;
        o4.y = (v4[j].y - mu) * rstd * gm.y + bt.y;
        o4.z = (v4[j].z - mu) * rstd * gm.z + bt.z;
        o4.w = (v4[j].w - mu) * rstd * gm.w + bt.w;
        *(float4*)&dst[d] = o4;
    }
}

// ---------------------------------------------------------------- kernel 4
// EMA: m[0]=ln[0]; m[t]=a*ln[t]+(1-a)*m[t-1]. (15/16)^256 ~ 7e-8, so
// chunks of 256 outputs with a 256-step lookback are independent.
// 128 threads per block (d quarter) for better wave balance.
__global__ void __launch_bounds__(128) k4_ema(float* __restrict__ out)
{
    const int d  = blockIdx.z * 128 + threadIdx.x;
    const int b  = blockIdx.y;
    const int t0 = blockIdx.x * 256;
    const float* src = g_actT + (b * SS) * DD + d;
    float* dst = out + (b * SS) * DD + d;
    const float a = 0.0625f, na = 0.9375f;
    float m;
    int t;
    if (t0 == 0) {
        m = src[0];
        dst[0] = m;
        t = 1;
    } else {
        m = 0.f;
        t = t0 - 256;
    }
    const int tend = t0 + 256;
    for (; t < t0; ++t) m = fmaf(na, m, a * src[t * DD]);      // lookback
    for (; t < tend; ++t) {
        m = fmaf(na, m, a * src[t * DD]);
        dst[t * DD] = m;
    }
}

// ---------------------------------------------------------------- launch
extern "C" void kernel_launch(void* const* d_in, const int* in_sizes, int n_in,
                              void* d_out, int out_size)
{
    const float* x     = (const float*)d_in[0];
    const float* ff    = (const float*)d_in[1];
    const float* cw    = (const float*)d_in[2];
    const float* cb    = (const float*)d_in[3];
    const float* gamma = (const float*)d_in[4];
    const float* beta  = (const float*)d_in[5];
    float* out = (float*)d_out;

    const int k1_smem = (GC * 264 + GC * KW * GC) * (int)sizeof(float);
    const int k2_smem = (4 * 2048 + 1024) * (int)sizeof(float2);
    cudaFuncSetAttribute(k1_conv, cudaFuncAttributeMaxDynamicSharedMemorySize, k1_smem);
    cudaFuncSetAttribute(k2_fft,  cudaFuncAttributeMaxDynamicSharedMemorySize, k2_smem);

    k0_norm<<<1, 256>>>(ff);
    k1_conv<<<dim3(SS / STILE, NGROUPS, BB), 512, k1_smem>>>(x, ff, cw, cb);
    k2_fft<<<dim3(DD / 8, BB), 512, k2_smem>>>();
    k3_ln<<<(BB * SS) / 16, 512>>>(gamma, beta);
    k4_ema<<<dim3(SS / 256, BB, 4), 128>>>(out);
}